// round 7
// baseline (speedup 1.0000x reference)
#include <cuda_runtime.h>
#include <math.h>
#include <stdint.h>

#define DD    4096
#define NT    512
#define NPV   2          // float4 groups per thread (NT*NPV*4 = DD)
#define VPT   8          // elements per thread
#define RPB   16         // rows per block
#define K16   16
#define CAPT  576
#define CAPB  320

#define TH_TOP 2.3f
#define TH_BOT 0.02f

__device__ float g_rstd[DD];   // 1/(std+eps)
__device__ float g_nmr[DD];    // -mean * rstd
__device__ float g_scal[8];    // 0:tau 1:beta_up 2:gamma 3:beta_fam 4:inv_norm_e

__device__ __forceinline__ float ex2a(float a) {
    float r; asm("ex2.approx.f32 %0, %1;" : "=f"(r) : "f"(a)); return r;
}
__device__ __forceinline__ float rcpa(float a) {
    float r; asm("rcp.approx.f32 %0, %1;" : "=f"(r) : "f"(a)); return r;
}

__global__ void prep_kernel(const float* __restrict__ ema_mean,
                            const float* __restrict__ ema_sq,
                            const float* __restrict__ ema_out,
                            const float* __restrict__ p_lt,
                            const float* __restrict__ p_lbu,
                            const float* __restrict__ p_lg,
                            const float* __restrict__ p_lbf) {
    __shared__ float sp[8];
    int tid = threadIdx.x;
    float acc = 0.0f;
    for (int i = tid; i < DD; i += 256) {
        float m = ema_mean[i];
        float v = fmaxf(ema_sq[i] - m * m, 1e-4f);
        float r = 1.0f / (sqrtf(v) + 1e-5f);
        g_rstd[i] = r;
        g_nmr[i]  = -m * r;
        float e = ema_out[i];
        acc = fmaf(e, e, acc);
    }
    #pragma unroll
    for (int o = 16; o; o >>= 1) acc += __shfl_xor_sync(0xffffffffu, acc, o);
    if ((tid & 31) == 0) sp[tid >> 5] = acc;
    __syncthreads();
    if (tid == 0) {
        float s = 0.0f;
        #pragma unroll
        for (int w = 0; w < 8; w++) s += sp[w];
        g_scal[0] = expf(p_lt[0]);                        // tau
        g_scal[1] = log1pf(expf(p_lbu[0]));               // beta_up
        g_scal[2] = log1pf(expf(p_lg[0]));                // gamma
        g_scal[3] = 1.0f / (1.0f + expf(-p_lbf[0]));      // beta_fam
        g_scal[4] = 1.0f / fmaxf(sqrtf(s), 1e-12f);       // 1/||ema_out||
    }
}

// descending insert into 8-deep sorted list r0..r7
#define INS8_TOP(v) do { float _l=(v), _u;                          \
    _u=fmaxf(r0,_l); _l=fminf(r0,_l); r0=_u;                        \
    _u=fmaxf(r1,_l); _l=fminf(r1,_l); r1=_u;                        \
    _u=fmaxf(r2,_l); _l=fminf(r2,_l); r2=_u;                        \
    _u=fmaxf(r3,_l); _l=fminf(r3,_l); r3=_u;                        \
    _u=fmaxf(r4,_l); _l=fminf(r4,_l); r4=_u;                        \
    _u=fmaxf(r5,_l); _l=fminf(r5,_l); r5=_u;                        \
    _u=fmaxf(r6,_l); _l=fminf(r6,_l); r6=_u;                        \
    r7=fmaxf(r7,_l); } while(0)

#define INS8_BOT(v) do { float _l=(v), _u;                          \
    _u=fminf(r0,_l); _l=fmaxf(r0,_l); r0=_u;                        \
    _u=fminf(r1,_l); _l=fmaxf(r1,_l); r1=_u;                        \
    _u=fminf(r2,_l); _l=fmaxf(r2,_l); r2=_u;                        \
    _u=fminf(r3,_l); _l=fmaxf(r3,_l); r3=_u;                        \
    _u=fminf(r4,_l); _l=fmaxf(r4,_l); r4=_u;                        \
    _u=fminf(r5,_l); _l=fmaxf(r5,_l); r5=_u;                        \
    _u=fminf(r6,_l); _l=fmaxf(r6,_l); r6=_u;                        \
    r7=fminf(r7,_l); } while(0)

__global__ __launch_bounds__(NT, 2)
void gelu_gate_kernel(const float* __restrict__ x,
                      const float* __restrict__ ema_out,
                      float* __restrict__ out,
                      int nrows) {
    __shared__ float s_tz[CAPT];
    __shared__ int   s_ti[CAPT];
    __shared__ float s_bz[CAPB];
    __shared__ int   s_bi[CAPB];
    __shared__ int   s_cnt[2];
    __shared__ float s_part[2 * (NT / 32)];
    __shared__ float s_res[4];   // 0:v16 1:w16 2:gc

    const int tid  = threadIdx.x;
    const int wid  = tid >> 5;
    const int lane = tid & 31;

    const float K0 = 2.0f * 0.7978845608028654f * 1.4426950408889634f;
    const float K1 = 2.0f * 0.044715f * 0.7978845608028654f * 1.4426950408889634f;
    const float INF = __int_as_float(0x7f800000);

    // ---- persistent per-column params (loaded once, reused for RPB rows) ----
    float rreg[VPT], nreg[VPT], ereg[VPT];
    #pragma unroll
    for (int i = 0; i < NPV; i++) {
        float4 rv = reinterpret_cast<const float4*>(g_rstd)[i * NT + tid];
        float4 nv = reinterpret_cast<const float4*>(g_nmr)[i * NT + tid];
        float4 ev = reinterpret_cast<const float4*>(ema_out)[i * NT + tid];
        rreg[i*4+0]=rv.x; rreg[i*4+1]=rv.y; rreg[i*4+2]=rv.z; rreg[i*4+3]=rv.w;
        nreg[i*4+0]=nv.x; nreg[i*4+1]=nv.y; nreg[i*4+2]=nv.z; nreg[i*4+3]=nv.w;
        ereg[i*4+0]=ev.x; ereg[i*4+1]=ev.y; ereg[i*4+2]=ev.z; ereg[i*4+3]=ev.w;
    }
    const float p_tau = g_scal[0];
    const float p_bu  = g_scal[1];
    const float p_gm  = g_scal[2];
    const float p_bf  = g_scal[3];
    const float p_ien = g_scal[4];

    if (tid == 0) { s_cnt[0] = 0; s_cnt[1] = 0; }
    __syncthreads();

    const int row0 = blockIdx.x * RPB;

    for (int rr = 0; rr < RPB; rr++) {
        const int row = row0 + rr;
        if (row >= nrows) break;
        const float4* xr = reinterpret_cast<const float4*>(x + (size_t)row * DD);
        float4* orr = reinterpret_cast<float4*>(out + (size_t)row * DD);

        float zbuf[VPT], gbuf[VPT];
        float s2 = 0.f, sd = 0.f;
        unsigned maskC = 0u;

        #pragma unroll
        for (int i = 0; i < NPV; i++) {
            float4 xv = xr[i * NT + tid];
            #pragma unroll
            for (int c = 0; c < 4; c++) {
                int j = i * 4 + c;
                float xx = (c==0)?xv.x:(c==1)?xv.y:(c==2)?xv.z:xv.w;
                float zz = fmaf(xx, rreg[j], nreg[j]);
                float x2 = xx * xx;
                float a  = xx * fmaf(x2, K1, K0);
                float e  = ex2a(a);
                float p  = fmaf(e, -1.0f, -1.0f);   // -(e+1)
                float d  = rcpa(p);                 // -1/(e+1)
                float gg = fmaf(xx, d, xx);         // x - x/(e+1)
                s2 = fmaf(gg, gg, s2);
                sd = fmaf(gg, ereg[j], sd);
                zbuf[j] = zz; gbuf[j] = gg;
                float az = fabsf(zz);
                maskC |= ((az > TH_TOP) | (az < TH_BOT)) ? (1u << j) : 0u;
            }
        }

        #pragma unroll
        for (int o = 16; o; o >>= 1) {
            s2 += __shfl_xor_sync(0xffffffffu, s2, o);
            sd += __shfl_xor_sync(0xffffffffu, sd, o);
        }
        if (lane == 0) {
            s_part[wid * 2 + 0] = s2;
            s_part[wid * 2 + 1] = sd;
        }

        // deferred pushes from register z (no reloads)
        while (maskC) {
            int j = __ffs(maskC) - 1;
            maskC &= maskC - 1;
            float zz = zbuf[j];
            float az = fabsf(zz);
            int idx = (((j >> 2) * NT + tid) << 2) + (j & 3);
            if (az > TH_TOP) {
                int p = atomicAdd(&s_cnt[0], 1);
                if (p < CAPT) { s_tz[p] = zz; s_ti[p] = idx; }
            } else {
                int p = atomicAdd(&s_cnt[1], 1);
                if (p < CAPB) { s_bz[p] = az; s_bi[p] = idx; }
            }
        }
        __syncthreads();   // A: candidates + partials visible

        // rare retry (block-uniform; rescans registers, cheap)
        {
            float thT = TH_TOP, thB = TH_BOT;
            for (int tries = 0; tries < 12; ++tries) {
                int ct = s_cnt[0], cb = s_cnt[1];
                bool badT = (ct < K16) | (ct > CAPT);
                bool badB = (cb < K16) | (cb > CAPB);
                if (!badT && !badB) break;
                if (badT) thT = (ct < K16) ? thT * 0.5f : thT * 1.4f;
                if (badB) thB = (cb < K16) ? thB * 2.0f : thB * 0.5f;
                __syncthreads();
                if (tid == 0) { if (badT) s_cnt[0] = 0; if (badB) s_cnt[1] = 0; }
                __syncthreads();
                #pragma unroll
                for (int j = 0; j < VPT; j++) {
                    float zz = zbuf[j];
                    float az = fabsf(zz);
                    int idx = (((j >> 2) * NT + tid) << 2) + (j & 3);
                    if (badT && az > thT) {
                        int p = atomicAdd(&s_cnt[0], 1);
                        if (p < CAPT) { s_tz[p] = zz; s_ti[p] = idx; }
                    }
                    if (badB && az < thB) {
                        int p = atomicAdd(&s_cnt[1], 1);
                        if (p < CAPB) { s_bz[p] = az; s_bi[p] = idx; }
                    }
                }
                __syncthreads();
            }
        }

        // selection: warp0 top-16th, warp1 bot-16th, warp2 cosine gate
        if (wid == 0) {
            int ct = min(s_cnt[0], CAPT);
            float r0=-1.f,r1=-1.f,r2=-1.f,r3=-1.f,r4=-1.f,r5=-1.f,r6=-1.f,r7=-1.f;
            for (int k = lane; k < ct; k += 32) {
                float v = fabsf(s_tz[k]);
                INS8_TOP(v);
            }
            float last = -1.f;
            #pragma unroll
            for (int it = 0; it < K16; it++) {
                float m = r0;
                #pragma unroll
                for (int o = 16; o; o >>= 1) m = fmaxf(m, __shfl_xor_sync(0xffffffffu, m, o));
                last = m;
                if (r0 == m) { r0=r1; r1=r2; r2=r3; r3=r4; r4=r5; r5=r6; r6=r7; r7=-1.f; }
            }
            if (lane == 0) s_res[0] = last;
        } else if (wid == 1) {
            int cb = min(s_cnt[1], CAPB);
            float r0=INF,r1=INF,r2=INF,r3=INF,r4=INF,r5=INF,r6=INF,r7=INF;
            for (int k = lane; k < cb; k += 32) {
                float v = s_bz[k];
                INS8_BOT(v);
            }
            float last = INF;
            #pragma unroll
            for (int it = 0; it < K16; it++) {
                float m = r0;
                #pragma unroll
                for (int o = 16; o; o >>= 1) m = fminf(m, __shfl_xor_sync(0xffffffffu, m, o));
                last = m;
                if (r0 == m) { r0=r1; r1=r2; r2=r3; r3=r4; r4=r5; r5=r6; r6=r7; r7=INF; }
            }
            if (lane == 0) s_res[1] = last;
        } else if (wid == 2) {
            float a = 0.f, b = 0.f;
            if (lane < NT / 32) { a = s_part[lane * 2]; b = s_part[lane * 2 + 1]; }
            #pragma unroll
            for (int o = 8; o; o >>= 1) {
                a += __shfl_xor_sync(0xffffffffu, a, o);
                b += __shfl_xor_sync(0xffffffffu, b, o);
            }
            if (lane == 0) {
                float nrm = fmaxf(sqrtf(a), 1e-12f);
                float cs  = fminf(fmaxf(b * p_ien / nrm, -1.0f), 1.0f);
                s_res[2] = __expf(-p_tau * cs);
            }
        }
        __syncthreads();   // B: thresholds + gc visible

        const float v16 = s_res[0];
        const float w16 = s_res[1];
        const float gc  = s_res[2];

        // epilogue: gate + store (rare tanh branch, mostly uniform not-taken)
        #pragma unroll
        for (int i = 0; i < NPV; i++) {
            float oa[4];
            #pragma unroll
            for (int c = 0; c < 4; c++) {
                int j = i * 4 + c;
                float zz = zbuf[j];
                float az = fabsf(zz);
                float gate = 1.0f;
                if (az >= v16) {
                    gate = fminf(fmaxf(fmaf(p_bu, tanhf(p_gm * zz), 1.0f), 0.1f), 8.0f);
                }
                if (az <= w16) gate = p_bf;
                oa[c] = gbuf[j] * gate * gc;
            }
            float4 ov; ov.x=oa[0]; ov.y=oa[1]; ov.z=oa[2]; ov.w=oa[3];
            orr[i * NT + tid] = ov;
        }

        if (tid == 0) { s_cnt[0] = 0; s_cnt[1] = 0; }   // safe: counts not read after B
        __syncthreads();   // C: row teardown — resets visible, s_res reads done
    }
}

extern "C" void kernel_launch(void* const* d_in, const int* in_sizes, int n_in,
                              void* d_out, int out_size) {
    const float* x        = (const float*)d_in[0];
    const float* ema_mean = (const float*)d_in[1];
    const float* ema_sq   = (const float*)d_in[2];
    const float* ema_out  = (const float*)d_in[3];
    const float* lt       = (const float*)d_in[4];
    const float* lbu      = (const float*)d_in[5];
    const float* lg       = (const float*)d_in[6];
    const float* lbf      = (const float*)d_in[7];
    float* out = (float*)d_out;

    int rows = in_sizes[0] / DD;
    if (rows < 1) rows = 1;
    int blocks = (rows + RPB - 1) / RPB;

    prep_kernel<<<1, 256>>>(ema_mean, ema_sq, ema_out, lt, lbu, lg, lbf);
    gelu_gate_kernel<<<blocks, NT>>>(x, ema_out, out, rows);
}

// round 8
// speedup vs baseline: 1.7380x; 1.7380x over previous
#include <cuda_runtime.h>
#include <cuda_bf16.h>
#include <math.h>
#include <stdint.h>

#define DD    4096
#define NT    256
#define NV4   4          // float4 groups per thread
#define VPT   16
#define K16   16
#define CAPT  576
#define CAPB  320

#define TH_TOP 2.3f
#define TH_BOT 0.02f

__device__ float    g_rstd[DD];   // exact 1/(std+eps)
__device__ float    g_nmr[DD];    // exact -mean*rstd
__device__ unsigned g_rn[DD];     // packed bf16: lo=rstd, hi=nmr (filter only)
__device__ float    g_scal[8];    // 0:tau 1:beta_up 2:gamma 3:beta_fam 4:inv_norm_e

__device__ __forceinline__ float ex2a(float a) {
    float r; asm("ex2.approx.f32 %0, %1;" : "=f"(r) : "f"(a)); return r;
}
__device__ __forceinline__ float rcpa(float a) {
    float r; asm("rcp.approx.f32 %0, %1;" : "=f"(r) : "f"(a)); return r;
}

__global__ void prep_kernel(const float* __restrict__ ema_mean,
                            const float* __restrict__ ema_sq,
                            const float* __restrict__ ema_out,
                            const float* __restrict__ p_lt,
                            const float* __restrict__ p_lbu,
                            const float* __restrict__ p_lg,
                            const float* __restrict__ p_lbf) {
    __shared__ float sp[8];
    int tid = threadIdx.x;
    float acc = 0.0f;
    for (int i = tid; i < DD; i += 256) {
        float m = ema_mean[i];
        float v = fmaxf(ema_sq[i] - m * m, 1e-4f);
        float r = 1.0f / (sqrtf(v) + 1e-5f);
        float n = -m * r;
        g_rstd[i] = r;
        g_nmr[i]  = n;
        unsigned lo = (unsigned)__bfloat16_as_ushort(__float2bfloat16(r));
        unsigned hi = (unsigned)__bfloat16_as_ushort(__float2bfloat16(n));
        g_rn[i] = lo | (hi << 16);
        float e = ema_out[i];
        acc = fmaf(e, e, acc);
    }
    #pragma unroll
    for (int o = 16; o; o >>= 1) acc += __shfl_xor_sync(0xffffffffu, acc, o);
    if ((tid & 31) == 0) sp[tid >> 5] = acc;
    __syncthreads();
    if (tid == 0) {
        float s = 0.0f;
        #pragma unroll
        for (int w = 0; w < 8; w++) s += sp[w];
        g_scal[0] = expf(p_lt[0]);                        // tau
        g_scal[1] = log1pf(expf(p_lbu[0]));               // beta_up
        g_scal[2] = log1pf(expf(p_lg[0]));                // gamma
        g_scal[3] = 1.0f / (1.0f + expf(-p_lbf[0]));      // beta_fam
        g_scal[4] = 1.0f / fmaxf(sqrtf(s), 1e-12f);       // 1/||ema_out||
    }
}

// descending insert into 8-deep sorted list r0..r7
#define INS8_TOP(v) do { float _l=(v), _u;                          \
    _u=fmaxf(r0,_l); _l=fminf(r0,_l); r0=_u;                        \
    _u=fmaxf(r1,_l); _l=fminf(r1,_l); r1=_u;                        \
    _u=fmaxf(r2,_l); _l=fminf(r2,_l); r2=_u;                        \
    _u=fmaxf(r3,_l); _l=fminf(r3,_l); r3=_u;                        \
    _u=fmaxf(r4,_l); _l=fminf(r4,_l); r4=_u;                        \
    _u=fmaxf(r5,_l); _l=fminf(r5,_l); r5=_u;                        \
    _u=fmaxf(r6,_l); _l=fminf(r6,_l); r6=_u;                        \
    r7=fmaxf(r7,_l); } while(0)

#define INS8_BOT(v) do { float _l=(v), _u;                          \
    _u=fminf(r0,_l); _l=fmaxf(r0,_l); r0=_u;                        \
    _u=fminf(r1,_l); _l=fmaxf(r1,_l); r1=_u;                        \
    _u=fminf(r2,_l); _l=fmaxf(r2,_l); r2=_u;                        \
    _u=fminf(r3,_l); _l=fmaxf(r3,_l); r3=_u;                        \
    _u=fminf(r4,_l); _l=fmaxf(r4,_l); r4=_u;                        \
    _u=fminf(r5,_l); _l=fmaxf(r5,_l); r5=_u;                        \
    _u=fminf(r6,_l); _l=fmaxf(r6,_l); r6=_u;                        \
    r7=fminf(r7,_l); } while(0)

__global__ __launch_bounds__(NT, 6)
void gelu_gate_kernel(const float* __restrict__ x,
                      const float* __restrict__ ema_out,
                      float* __restrict__ out) {
    __shared__ float s_tz[CAPT];   // exact z of top candidates
    __shared__ int   s_ti[CAPT];
    __shared__ float s_bz[CAPB];   // exact |z| of bottom candidates
    __shared__ int   s_bi[CAPB];
    __shared__ int   s_cnt[2];
    __shared__ float s_part[2 * (NT / 32)];

    const int tid = threadIdx.x;
    const float* xrow = x + (size_t)blockIdx.x * DD;
    const float4* xr = reinterpret_cast<const float4*>(xrow);
    const uint4*  pr = reinterpret_cast<const uint4*>(g_rn);
    const float4* er = reinterpret_cast<const float4*>(ema_out);
    float* orow = out + (size_t)blockIdx.x * DD;
    float4* orow4 = reinterpret_cast<float4*>(orow);

    // gelu(x) = x - x/(exp2(x*(K0+K1*x^2))+1)
    const float K0 = 2.0f * 0.7978845608028654f * 1.4426950408889634f;
    const float K1 = 2.0f * 0.044715f * 0.7978845608028654f * 1.4426950408889634f;
    const float INF = __int_as_float(0x7f800000);

    if (tid == 0) { s_cnt[0] = 0; s_cnt[1] = 0; }
    __syncthreads();

    float gbuf[VPT];
    float s2 = 0.f, sd = 0.f;
    unsigned maskC = 0u;

    #pragma unroll
    for (int i = 0; i < NV4; i++) {
        int idx4 = i * NT + tid;
        float4 xv = xr[idx4];
        uint4  uv = pr[idx4];
        float4 ev = er[idx4];
        #pragma unroll
        for (int c = 0; c < 4; c++) {
            int j = i * 4 + c;
            float    xx = (c==0)?xv.x:(c==1)?xv.y:(c==2)?xv.z:xv.w;
            unsigned uu = (c==0)?uv.x:(c==1)?uv.y:(c==2)?uv.z:uv.w;
            float    ee = (c==0)?ev.x:(c==1)?ev.y:(c==2)?ev.z:ev.w;
            float rA = __uint_as_float(uu << 16);          // bf16 rstd
            float nA = __uint_as_float(uu & 0xffff0000u);  // bf16 nmr
            float zA = fmaf(xx, rA, nA);                   // approx z (filter only)
            float x2 = xx * xx;
            float aa = xx * fmaf(x2, K1, K0);
            float e  = ex2a(aa);
            float p  = fmaf(e, -1.0f, -1.0f);              // -(e+1)
            float d  = rcpa(p);                            // -1/(e+1)
            float gg = fmaf(xx, d, xx);                    // x - x/(e+1)
            s2 = fmaf(gg, gg, s2);
            sd = fmaf(gg, ee, sd);
            gbuf[j] = gg;
            float az = fabsf(zA);
            maskC |= ((az > TH_TOP) | (az < TH_BOT)) ? (1u << j) : 0u;
        }
    }

    #pragma unroll
    for (int o = 16; o; o >>= 1) {
        s2 += __shfl_xor_sync(0xffffffffu, s2, o);
        sd += __shfl_xor_sync(0xffffffffu, sd, o);
    }
    if ((tid & 31) == 0) {
        s_part[(tid >> 5) * 2 + 0] = s2;
        s_part[(tid >> 5) * 2 + 1] = sd;
    }

    // ---- deferred pushes: compute EXACT z from fp32 stats (rare, ~0.9/thread) ----
    while (maskC) {
        int j = __ffs(maskC) - 1;
        maskC &= maskC - 1;
        int idx = (((j >> 2) * NT + tid) << 2) + (j & 3);
        float xx = __ldg(xrow + idx);
        float zz = fmaf(xx, __ldg(g_rstd + idx), __ldg(g_nmr + idx));
        float az = fabsf(zz);
        if (az > TH_TOP) {
            int p = atomicAdd(&s_cnt[0], 1);
            if (p < CAPT) { s_tz[p] = zz; s_ti[p] = idx; }
        } else if (az < TH_BOT) {
            int p = atomicAdd(&s_cnt[1], 1);
            if (p < CAPB) { s_bz[p] = az; s_bi[p] = idx; }
        }
        // (bf16 boundary stragglers that fail the exact test are simply dropped)
    }
    __syncthreads();   // barrier A

    // ---- rare retry loop (block-uniform; normally breaks immediately) ----
    {
        float thT = TH_TOP, thB = TH_BOT;
        for (int tries = 0; tries < 12; ++tries) {
            int ct = s_cnt[0], cb = s_cnt[1];
            bool badT = (ct < K16) | (ct > CAPT);
            bool badB = (cb < K16) | (cb > CAPB);
            if (!badT && !badB) break;
            if (badT) thT = (ct < K16) ? thT * 0.5f : thT * 1.4f;
            if (badB) thB = (cb < K16) ? thB * 2.0f : thB * 0.5f;
            __syncthreads();
            if (tid == 0) { if (badT) s_cnt[0] = 0; if (badB) s_cnt[1] = 0; }
            __syncthreads();
            for (int i = 0; i < NV4; i++) {
                int idx4 = i * NT + tid;
                float4 xv = xr[idx4];
                #pragma unroll
                for (int c = 0; c < 4; c++) {
                    int idx = idx4 * 4 + c;
                    float xx = (c==0)?xv.x:(c==1)?xv.y:(c==2)?xv.z:xv.w;
                    float zz = fmaf(xx, __ldg(g_rstd + idx), __ldg(g_nmr + idx));
                    float az = fabsf(zz);
                    if (badT && az > thT) {
                        int p = atomicAdd(&s_cnt[0], 1);
                        if (p < CAPT) { s_tz[p] = zz; s_ti[p] = idx; }
                    }
                    if (badB && az < thB) {
                        int p = atomicAdd(&s_cnt[1], 1);
                        if (p < CAPB) { s_bz[p] = az; s_bi[p] = idx; }
                    }
                }
            }
            __syncthreads();
        }
    }

    // ---- cosine gate (every thread) ----
    float a = 0.f, b = 0.f;
    #pragma unroll
    for (int w = 0; w < NT / 32; w++) { a += s_part[2*w]; b += s_part[2*w+1]; }
    float nrm = fmaxf(sqrtf(a), 1e-12f);
    float cs  = fminf(fmaxf(b * g_scal[4] / nrm, -1.0f), 1.0f);
    const float gc = __expf(-g_scal[0] * cs);

    // ---- bulk store from registers: out = g * gc ----
    #pragma unroll
    for (int i = 0; i < NV4; i++) {
        float4 ov;
        ov.x = gbuf[i*4+0] * gc;
        ov.y = gbuf[i*4+1] * gc;
        ov.z = gbuf[i*4+2] * gc;
        ov.w = gbuf[i*4+3] * gc;
        orow4[i * NT + tid] = ov;
    }
    __syncthreads();   // barrier B: all bulk stores done before patching

    // ---- selection + global patch (<=32 elements) ----
    const int wid = tid >> 5, lane = tid & 31;
    if (wid == 0) {
        int ct = min(s_cnt[0], CAPT);
        float r0=-1.f,r1=-1.f,r2=-1.f,r3=-1.f,r4=-1.f,r5=-1.f,r6=-1.f,r7=-1.f;
        for (int k = lane; k < ct; k += 32) {
            float v = fabsf(s_tz[k]);
            INS8_TOP(v);
        }
        float last = -1.f;
        #pragma unroll
        for (int it = 0; it < K16; it++) {
            float m = r0;
            #pragma unroll
            for (int o = 16; o; o >>= 1) m = fmaxf(m, __shfl_xor_sync(0xffffffffu, m, o));
            last = m;
            if (r0 == m) { r0=r1; r1=r2; r2=r3; r3=r4; r4=r5; r5=r6; r6=r7; r7=-1.f; }
        }
        const float v16 = last;
        const float bu = g_scal[1];
        const float gm = g_scal[2];
        for (int k = lane; k < ct; k += 32) {
            float zz = s_tz[k];
            if (fabsf(zz) >= v16) {
                int idx = s_ti[k];
                float gate = fminf(fmaxf(fmaf(bu, tanhf(gm * zz), 1.0f), 0.1f), 8.0f);
                orow[idx] = orow[idx] * gate;
            }
        }
    } else if (wid == 1) {
        int cb = min(s_cnt[1], CAPB);
        float r0=INF,r1=INF,r2=INF,r3=INF,r4=INF,r5=INF,r6=INF,r7=INF;
        for (int k = lane; k < cb; k += 32) {
            float v = s_bz[k];
            INS8_BOT(v);
        }
        float last = INF;
        #pragma unroll
        for (int it = 0; it < K16; it++) {
            float m = r0;
            #pragma unroll
            for (int o = 16; o; o >>= 1) m = fminf(m, __shfl_xor_sync(0xffffffffu, m, o));
            last = m;
            if (r0 == m) { r0=r1; r1=r2; r2=r3; r3=r4; r4=r5; r5=r6; r6=r7; r7=INF; }
        }
        const float w16 = last;
        const float bf = g_scal[3];
        for (int k = lane; k < cb; k += 32) {
            if (s_bz[k] <= w16) {
                int idx = s_bi[k];
                orow[idx] = orow[idx] * bf;
            }
        }
    }
}

extern "C" void kernel_launch(void* const* d_in, const int* in_sizes, int n_in,
                              void* d_out, int out_size) {
    const float* x        = (const float*)d_in[0];
    const float* ema_mean = (const float*)d_in[1];
    const float* ema_sq   = (const float*)d_in[2];
    const float* ema_out  = (const float*)d_in[3];
    const float* lt       = (const float*)d_in[4];
    const float* lbu      = (const float*)d_in[5];
    const float* lg       = (const float*)d_in[6];
    const float* lbf      = (const float*)d_in[7];
    float* out = (float*)d_out;

    int rows = in_sizes[0] / DD;
    if (rows < 1) rows = 1;

    prep_kernel<<<1, 256>>>(ema_mean, ema_sq, ema_out, lt, lbu, lg, lbf);
    gelu_gate_kernel<<<rows, NT>>>(x, ema_out, out);
}

// round 9
// speedup vs baseline: 1.7552x; 1.0099x over previous
#include <cuda_runtime.h>
#include <cuda_bf16.h>
#include <math.h>
#include <stdint.h>

#define DD    4096
#define NT    256
#define NV4   4          // float4 groups per thread
#define VPT   16
#define K16   16
#define CAPT  224
#define CAPB  192

#define TH_TOP 2.7f
#define TH_BOT 0.02f

__device__ float           g_rstd[DD];     // exact 1/(std+eps)
__device__ float           g_nmr[DD];      // exact -mean*rstd
__device__ __nv_bfloat162  g_rp2[DD / 2];  // bf16 rstd pairs (filter only)
__device__ __nv_bfloat162  g_np2[DD / 2];  // bf16 nmr pairs (filter only)
__device__ float           g_scal[8];      // 0:tau 1:beta_up 2:gamma 3:beta_fam 4:inv_norm_e

__device__ __forceinline__ float tanha(float a) {
    float r; asm("tanh.approx.f32 %0, %1;" : "=f"(r) : "f"(a)); return r;
}
__device__ __forceinline__ __nv_bfloat162 u2b(unsigned u) {
    return *reinterpret_cast<__nv_bfloat162*>(&u);
}
__device__ __forceinline__ unsigned b2u(__nv_bfloat162 h) {
    return *reinterpret_cast<unsigned*>(&h);
}

__global__ void prep_kernel(const float* __restrict__ ema_mean,
                            const float* __restrict__ ema_sq,
                            const float* __restrict__ ema_out,
                            const float* __restrict__ p_lt,
                            const float* __restrict__ p_lbu,
                            const float* __restrict__ p_lg,
                            const float* __restrict__ p_lbf) {
    __shared__ float sp[8];
    int tid = threadIdx.x;
    float acc = 0.0f;
    __nv_bfloat16* rp = reinterpret_cast<__nv_bfloat16*>(g_rp2);
    __nv_bfloat16* np = reinterpret_cast<__nv_bfloat16*>(g_np2);
    for (int i = tid; i < DD; i += 256) {
        float m = ema_mean[i];
        float v = fmaxf(ema_sq[i] - m * m, 1e-4f);
        float r = 1.0f / (sqrtf(v) + 1e-5f);
        float n = -m * r;
        g_rstd[i] = r;
        g_nmr[i]  = n;
        rp[i] = __float2bfloat16(r);
        np[i] = __float2bfloat16(n);
        float e = ema_out[i];
        acc = fmaf(e, e, acc);
    }
    #pragma unroll
    for (int o = 16; o; o >>= 1) acc += __shfl_xor_sync(0xffffffffu, acc, o);
    if ((tid & 31) == 0) sp[tid >> 5] = acc;
    __syncthreads();
    if (tid == 0) {
        float s = 0.0f;
        #pragma unroll
        for (int w = 0; w < 8; w++) s += sp[w];
        g_scal[0] = expf(p_lt[0]);                        // tau
        g_scal[1] = log1pf(expf(p_lbu[0]));               // beta_up
        g_scal[2] = log1pf(expf(p_lg[0]));                // gamma
        g_scal[3] = 1.0f / (1.0f + expf(-p_lbf[0]));      // beta_fam
        g_scal[4] = 1.0f / fmaxf(sqrtf(s), 1e-12f);       // 1/||ema_out||
    }
}

// descending insert into 8-deep sorted list r0..r7
#define INS8_TOP(v) do { float _l=(v), _u;                          \
    _u=fmaxf(r0,_l); _l=fminf(r0,_l); r0=_u;                        \
    _u=fmaxf(r1,_l); _l=fminf(r1,_l); r1=_u;                        \
    _u=fmaxf(r2,_l); _l=fminf(r2,_l); r2=_u;                        \
    _u=fmaxf(r3,_l); _l=fminf(r3,_l); r3=_u;                        \
    _u=fmaxf(r4,_l); _l=fminf(r4,_l); r4=_u;                        \
    _u=fmaxf(r5,_l); _l=fminf(r5,_l); r5=_u;                        \
    _u=fmaxf(r6,_l); _l=fminf(r6,_l); r6=_u;                        \
    r7=fmaxf(r7,_l); } while(0)

#define INS8_BOT(v) do { float _l=(v), _u;                          \
    _u=fminf(r0,_l); _l=fmaxf(r0,_l); r0=_u;                        \
    _u=fminf(r1,_l); _l=fmaxf(r1,_l); r1=_u;                        \
    _u=fminf(r2,_l); _l=fmaxf(r2,_l); r2=_u;                        \
    _u=fminf(r3,_l); _l=fmaxf(r3,_l); r3=_u;                        \
    _u=fminf(r4,_l); _l=fmaxf(r4,_l); r4=_u;                        \
    _u=fminf(r5,_l); _l=fmaxf(r5,_l); r5=_u;                        \
    _u=fminf(r6,_l); _l=fmaxf(r6,_l); r6=_u;                        \
    r7=fminf(r7,_l); } while(0)

__global__ __launch_bounds__(NT, 6)
void gelu_gate_kernel(const float* __restrict__ x,
                      const float* __restrict__ ema_out,
                      float* __restrict__ out) {
    __shared__ float s_tz[CAPT];
    __shared__ int   s_ti[CAPT];
    __shared__ float s_bz[CAPB];
    __shared__ int   s_bi[CAPB];
    __shared__ int   s_cnt[2];
    __shared__ float s_part[2 * (NT / 32)];

    const int tid = threadIdx.x;
    const float* xrow = x + (size_t)blockIdx.x * DD;
    const float4* xr = reinterpret_cast<const float4*>(xrow);
    const uint2*  rpu = reinterpret_cast<const uint2*>(g_rp2);  // 2 pairs = 4 elems
    const uint2*  npu = reinterpret_cast<const uint2*>(g_np2);
    const float4* er  = reinterpret_cast<const float4*>(ema_out);
    float* orow = out + (size_t)blockIdx.x * DD;
    float4* orow4 = reinterpret_cast<float4*>(orow);

    const float G0 = 0.7978845608028654f;
    const float G1 = 0.044715f * 0.7978845608028654f;
    const float INF = __int_as_float(0x7f800000);
    const __nv_bfloat162 TT2 = __float2bfloat162_rn(TH_TOP);
    const __nv_bfloat162 TB2 = __float2bfloat162_rn(TH_BOT);

    if (tid == 0) { s_cnt[0] = 0; s_cnt[1] = 0; }
    __syncthreads();

    float gbuf[VPT];
    float s2 = 0.f, sd = 0.f;
    unsigned maskP = 0u;   // one bit per element-PAIR (8 pairs)

    #pragma unroll
    for (int i = 0; i < NV4; i++) {
        int idx4 = i * NT + tid;
        float4 xv = xr[idx4];
        uint2  rp = rpu[idx4];
        uint2  np = npu[idx4];
        float4 ev = er[idx4];
        // gelu (tanh.approx)
        #pragma unroll
        for (int c = 0; c < 4; c++) {
            int j = i * 4 + c;
            float xx = (c==0)?xv.x:(c==1)?xv.y:(c==2)?xv.z:xv.w;
            float ee = (c==0)?ev.x:(c==1)?ev.y:(c==2)?ev.z:ev.w;
            float x2 = xx * xx;
            float u  = xx * fmaf(x2, G1, G0);
            float t  = tanha(u);
            float hx = 0.5f * xx;
            float gg = fmaf(hx, t, hx);
            s2 = fmaf(gg, gg, s2);
            sd = fmaf(gg, ee, sd);
            gbuf[j] = gg;
        }
        // bf16x2 z-filter (pair granularity)
        #pragma unroll
        for (int p = 0; p < 2; p++) {
            __nv_bfloat162 xp = (p==0) ? __floats2bfloat162_rn(xv.x, xv.y)
                                       : __floats2bfloat162_rn(xv.z, xv.w);
            __nv_bfloat162 zb = __hfma2(xp, u2b(p==0?rp.x:rp.y), u2b(p==0?np.x:np.y));
            __nv_bfloat162 ab = __habs2(zb);
            unsigned hitw = b2u(__hgt2(ab, TT2)) | b2u(__hlt2(ab, TB2));
            maskP |= hitw ? (1u << (i * 2 + p)) : 0u;
        }
    }

    #pragma unroll
    for (int o = 16; o; o >>= 1) {
        s2 += __shfl_xor_sync(0xffffffffu, s2, o);
        sd += __shfl_xor_sync(0xffffffffu, sd, o);
    }
    if ((tid & 31) == 0) {
        s_part[(tid >> 5) * 2 + 0] = s2;
        s_part[(tid >> 5) * 2 + 1] = sd;
    }

    // ---- deferred pushes: exact fp32 z recheck for both halves of hit pairs ----
    while (maskP) {
        int pr = __ffs(maskP) - 1;
        maskP &= maskP - 1;
        int i = pr >> 1, p = pr & 1;
        int base = (((i * NT) + tid) << 2) + p * 2;
        #pragma unroll
        for (int h = 0; h < 2; h++) {
            int idx = base + h;
            float xx = __ldg(xrow + idx);
            float zz = fmaf(xx, __ldg(g_rstd + idx), __ldg(g_nmr + idx));
            float az = fabsf(zz);
            if (az > TH_TOP) {
                int q = atomicAdd(&s_cnt[0], 1);
                if (q < CAPT) { s_tz[q] = zz; s_ti[q] = idx; }
            } else if (az < TH_BOT) {
                int q = atomicAdd(&s_cnt[1], 1);
                if (q < CAPB) { s_bz[q] = az; s_bi[q] = idx; }
            }
        }
    }
    __syncthreads();   // barrier A

    // ---- rare retry loop (block-uniform, exact rescan; normally breaks) ----
    {
        float thT = TH_TOP, thB = TH_BOT;
        for (int tries = 0; tries < 12; ++tries) {
            int ct = s_cnt[0], cb = s_cnt[1];
            bool badT = (ct < K16) | (ct > CAPT);
            bool badB = (cb < K16) | (cb > CAPB);
            if (!badT && !badB) break;
            if (badT) thT = (ct < K16) ? thT * 0.5f : thT * 1.4f;
            if (badB) thB = (cb < K16) ? thB * 2.0f : thB * 0.5f;
            __syncthreads();
            if (tid == 0) { if (badT) s_cnt[0] = 0; if (badB) s_cnt[1] = 0; }
            __syncthreads();
            for (int i = 0; i < NV4; i++) {
                int idx4 = i * NT + tid;
                float4 xv = xr[idx4];
                #pragma unroll
                for (int c = 0; c < 4; c++) {
                    int idx = idx4 * 4 + c;
                    float xx = (c==0)?xv.x:(c==1)?xv.y:(c==2)?xv.z:xv.w;
                    float zz = fmaf(xx, __ldg(g_rstd + idx), __ldg(g_nmr + idx));
                    float az = fabsf(zz);
                    if (badT && az > thT) {
                        int q = atomicAdd(&s_cnt[0], 1);
                        if (q < CAPT) { s_tz[q] = zz; s_ti[q] = idx; }
                    }
                    if (badB && az < thB) {
                        int q = atomicAdd(&s_cnt[1], 1);
                        if (q < CAPB) { s_bz[q] = az; s_bi[q] = idx; }
                    }
                }
            }
            __syncthreads();
        }
    }

    // ---- cosine gate (every thread; rsqrt instead of div) ----
    float a = 0.f, b = 0.f;
    #pragma unroll
    for (int w = 0; w < NT / 32; w++) { a += s_part[2*w]; b += s_part[2*w+1]; }
    float inv = rsqrtf(fmaxf(a, 1e-24f));
    float cs  = fminf(fmaxf(b * g_scal[4] * inv, -1.0f), 1.0f);
    const float gc = __expf(-g_scal[0] * cs);

    // ---- bulk store from registers: out = g * gc ----
    #pragma unroll
    for (int i = 0; i < NV4; i++) {
        float4 ov;
        ov.x = gbuf[i*4+0] * gc;
        ov.y = gbuf[i*4+1] * gc;
        ov.z = gbuf[i*4+2] * gc;
        ov.w = gbuf[i*4+3] * gc;
        orow4[i * NT + tid] = ov;
    }
    __syncthreads();   // barrier B: bulk stores done before patching

    // ---- selection + global patch (<=32 elements) ----
    const int wid = tid >> 5, lane = tid & 31;
    if (wid == 0) {
        int ct = min(s_cnt[0], CAPT);
        float r0=-1.f,r1=-1.f,r2=-1.f,r3=-1.f,r4=-1.f,r5=-1.f,r6=-1.f,r7=-1.f;
        for (int k = lane; k < ct; k += 32) {
            float v = fabsf(s_tz[k]);
            INS8_TOP(v);
        }
        float last = -1.f;
        #pragma unroll
        for (int it = 0; it < K16; it++) {
            float m = r0;
            #pragma unroll
            for (int o = 16; o; o >>= 1) m = fmaxf(m, __shfl_xor_sync(0xffffffffu, m, o));
            last = m;
            if (r0 == m) { r0=r1; r1=r2; r2=r3; r3=r4; r4=r5; r5=r6; r6=r7; r7=-1.f; }
        }
        const float v16 = last;
        const float bu = g_scal[1];
        const float gm = g_scal[2];
        for (int k = lane; k < ct; k += 32) {
            float zz = s_tz[k];
            if (fabsf(zz) >= v16) {
                int idx = s_ti[k];
                float gate = fminf(fmaxf(fmaf(bu, tanhf(gm * zz), 1.0f), 0.1f), 8.0f);
                orow[idx] = orow[idx] * gate;
            }
        }
    } else if (wid == 1) {
        int cb = min(s_cnt[1], CAPB);
        float r0=INF,r1=INF,r2=INF,r3=INF,r4=INF,r5=INF,r6=INF,r7=INF;
        for (int k = lane; k < cb; k += 32) {
            float v = s_bz[k];
            INS8_BOT(v);
        }
        float last = INF;
        #pragma unroll
        for (int it = 0; it < K16; it++) {
            float m = r0;
            #pragma unroll
            for (int o = 16; o; o >>= 1) m = fminf(m, __shfl_xor_sync(0xffffffffu, m, o));
            last = m;
            if (r0 == m) { r0=r1; r1=r2; r2=r3; r3=r4; r4=r5; r5=r6; r6=r7; r7=INF; }
        }
        const float w16 = last;
        const float bf = g_scal[3];
        for (int k = lane; k < cb; k += 32) {
            if (s_bz[k] <= w16) {
                int idx = s_bi[k];
                orow[idx] = orow[idx] * bf;
            }
        }
    }
}

extern "C" void kernel_launch(void* const* d_in, const int* in_sizes, int n_in,
                              void* d_out, int out_size) {
    const float* x        = (const float*)d_in[0];
    const float* ema_mean = (const float*)d_in[1];
    const float* ema_sq   = (const float*)d_in[2];
    const float* ema_out  = (const float*)d_in[3];
    const float* lt       = (const float*)d_in[4];
    const float* lbu      = (const float*)d_in[5];
    const float* lg       = (const float*)d_in[6];
    const float* lbf      = (const float*)d_in[7];
    float* out = (float*)d_out;

    int rows = in_sizes[0] / DD;
    if (rows < 1) rows = 1;

    prep_kernel<<<1, 256>>>(ema_mean, ema_sq, ema_out, lt, lbu, lg, lbf);
    gelu_gate_kernel<<<rows, NT>>>(x, ema_out, out);
}

// round 10
// speedup vs baseline: 1.9253x; 1.0969x over previous
#include <cuda_runtime.h>
#include <cuda_bf16.h>
#include <cuda_fp16.h>
#include <math.h>
#include <stdint.h>

#define DD    4096
#define NT    256
#define NV4   4          // float4 groups per thread
#define K16   16
#define CAPT  224
#define CAPB  192

#define TH_TOP 2.7f
#define TH_BOT 0.02f

__device__ float    g_rstd[DD];     // exact 1/(std+eps)
__device__ float    g_nmr[DD];      // exact -mean*rstd
__device__ uint4    g_rn4[DD / 4];  // bf16 pairs: {r01, n01, r23, n23} per 4 elems
__device__ float    g_scal[8];      // 0:tau 1:beta_up 2:gamma 3:beta_fam 4:inv_norm_e

__device__ __forceinline__ float tanha(float a) {
    float r; asm("tanh.approx.f32 %0, %1;" : "=f"(r) : "f"(a)); return r;
}
__device__ __forceinline__ __nv_bfloat162 u2b(unsigned u) {
    return *reinterpret_cast<__nv_bfloat162*>(&u);
}
__device__ __forceinline__ unsigned b2u(__nv_bfloat162 h) {
    return *reinterpret_cast<unsigned*>(&h);
}

__global__ void prep_kernel(const float* __restrict__ ema_mean,
                            const float* __restrict__ ema_sq,
                            const float* __restrict__ ema_out,
                            const float* __restrict__ p_lt,
                            const float* __restrict__ p_lbu,
                            const float* __restrict__ p_lg,
                            const float* __restrict__ p_lbf) {
    __shared__ float sp[8];
    int tid = threadIdx.x;
    float acc = 0.0f;
    for (int i4 = tid; i4 < DD / 4; i4 += 256) {
        float r[4], n[4];
        #pragma unroll
        for (int c = 0; c < 4; c++) {
            int i = i4 * 4 + c;
            float m = ema_mean[i];
            float v = fmaxf(ema_sq[i] - m * m, 1e-4f);
            float rr = 1.0f / (sqrtf(v) + 1e-5f);
            float nn = -m * rr;
            g_rstd[i] = rr;
            g_nmr[i]  = nn;
            r[c] = rr; n[c] = nn;
            float e = ema_out[i];
            acc = fmaf(e, e, acc);
        }
        uint4 u;
        u.x = b2u(__floats2bfloat162_rn(r[0], r[1]));
        u.y = b2u(__floats2bfloat162_rn(n[0], n[1]));
        u.z = b2u(__floats2bfloat162_rn(r[2], r[3]));
        u.w = b2u(__floats2bfloat162_rn(n[2], n[3]));
        g_rn4[i4] = u;
    }
    #pragma unroll
    for (int o = 16; o; o >>= 1) acc += __shfl_xor_sync(0xffffffffu, acc, o);
    if ((tid & 31) == 0) sp[tid >> 5] = acc;
    __syncthreads();
    if (tid == 0) {
        float s = 0.0f;
        #pragma unroll
        for (int w = 0; w < 8; w++) s += sp[w];
        g_scal[0] = expf(p_lt[0]);                        // tau
        g_scal[1] = log1pf(expf(p_lbu[0]));               // beta_up
        g_scal[2] = log1pf(expf(p_lg[0]));                // gamma
        g_scal[3] = 1.0f / (1.0f + expf(-p_lbf[0]));      // beta_fam
        g_scal[4] = 1.0f / fmaxf(sqrtf(s), 1e-12f);       // 1/||ema_out||
    }
}

// descending insert into 8-deep sorted list r0..r7
#define INS8_TOP(v) do { float _l=(v), _u;                          \
    _u=fmaxf(r0,_l); _l=fminf(r0,_l); r0=_u;                        \
    _u=fmaxf(r1,_l); _l=fminf(r1,_l); r1=_u;                        \
    _u=fmaxf(r2,_l); _l=fminf(r2,_l); r2=_u;                        \
    _u=fmaxf(r3,_l); _l=fminf(r3,_l); r3=_u;                        \
    _u=fmaxf(r4,_l); _l=fminf(r4,_l); r4=_u;                        \
    _u=fmaxf(r5,_l); _l=fminf(r5,_l); r5=_u;                        \
    _u=fmaxf(r6,_l); _l=fminf(r6,_l); r6=_u;                        \
    r7=fmaxf(r7,_l); } while(0)

#define INS8_BOT(v) do { float _l=(v), _u;                          \
    _u=fminf(r0,_l); _l=fmaxf(r0,_l); r0=_u;                        \
    _u=fminf(r1,_l); _l=fmaxf(r1,_l); r1=_u;                        \
    _u=fminf(r2,_l); _l=fmaxf(r2,_l); r2=_u;                        \
    _u=fminf(r3,_l); _l=fmaxf(r3,_l); r3=_u;                        \
    _u=fminf(r4,_l); _l=fmaxf(r4,_l); r4=_u;                        \
    _u=fminf(r5,_l); _l=fmaxf(r5,_l); r5=_u;                        \
    _u=fminf(r6,_l); _l=fmaxf(r6,_l); r6=_u;                        \
    r7=fminf(r7,_l); } while(0)

__global__ __launch_bounds__(NT, 7)
void gelu_gate_kernel(const float* __restrict__ x,
                      const float* __restrict__ ema_out,
                      float* __restrict__ out) {
    __shared__ float s_tz[CAPT];
    __shared__ int   s_ti[CAPT];
    __shared__ float s_bz[CAPB];
    __shared__ int   s_bi[CAPB];
    __shared__ int   s_cnt[2];
    __shared__ float s_part[2 * (NT / 32)];

    const int tid = threadIdx.x;
    const float* xrow = x + (size_t)blockIdx.x * DD;
    const float4* xr  = reinterpret_cast<const float4*>(xrow);
    const uint4*  rn  = g_rn4;
    const float4* er  = reinterpret_cast<const float4*>(ema_out);
    float* orow = out + (size_t)blockIdx.x * DD;
    float4* orow4 = reinterpret_cast<float4*>(orow);

    const float G0 = 0.7978845608028654f;
    const float G1 = 0.044715f * 0.7978845608028654f;
    const float INF = __int_as_float(0x7f800000);
    const __nv_bfloat162 TT2 = __float2bfloat162_rn(TH_TOP);
    const __nv_bfloat162 TB2 = __float2bfloat162_rn(TH_BOT);

    if (tid == 0) { s_cnt[0] = 0; s_cnt[1] = 0; }
    __syncthreads();

    __half2 gh[2 * NV4];     // packed gelu values (8 regs)
    float s2 = 0.f, sd = 0.f;
    unsigned maskP = 0u;     // one bit per element-pair (8 pairs)

    #pragma unroll
    for (int i = 0; i < NV4; i++) {
        int idx4 = i * NT + tid;
        float4 xv = xr[idx4];
        uint4  rv = rn[idx4];
        float4 ev = er[idx4];
        float gg[4];
        #pragma unroll
        for (int c = 0; c < 4; c++) {
            float xx = (c==0)?xv.x:(c==1)?xv.y:(c==2)?xv.z:xv.w;
            float ee = (c==0)?ev.x:(c==1)?ev.y:(c==2)?ev.z:ev.w;
            float x2 = xx * xx;
            float u  = xx * fmaf(x2, G1, G0);
            float t  = tanha(u);
            float hx = 0.5f * xx;
            float g  = fmaf(hx, t, hx);
            s2 = fmaf(g, g, s2);
            sd = fmaf(g, ee, sd);
            gg[c] = g;
        }
        gh[i*2+0] = __floats2half2_rn(gg[0], gg[1]);
        gh[i*2+1] = __floats2half2_rn(gg[2], gg[3]);
        // bf16x2 z-filter at pair granularity
        {
            __nv_bfloat162 xp0 = __floats2bfloat162_rn(xv.x, xv.y);
            __nv_bfloat162 xp1 = __floats2bfloat162_rn(xv.z, xv.w);
            __nv_bfloat162 z0 = __hfma2(xp0, u2b(rv.x), u2b(rv.y));
            __nv_bfloat162 z1 = __hfma2(xp1, u2b(rv.z), u2b(rv.w));
            __nv_bfloat162 a0 = __habs2(z0);
            __nv_bfloat162 a1 = __habs2(z1);
            unsigned h0 = b2u(__hgt2(a0, TT2)) | b2u(__hlt2(a0, TB2));
            unsigned h1 = b2u(__hgt2(a1, TT2)) | b2u(__hlt2(a1, TB2));
            maskP |= h0 ? (1u << (i*2+0)) : 0u;
            maskP |= h1 ? (1u << (i*2+1)) : 0u;
        }
    }

    #pragma unroll
    for (int o = 16; o; o >>= 1) {
        s2 += __shfl_xor_sync(0xffffffffu, s2, o);
        sd += __shfl_xor_sync(0xffffffffu, sd, o);
    }
    if ((tid & 31) == 0) {
        s_part[(tid >> 5) * 2 + 0] = s2;
        s_part[(tid >> 5) * 2 + 1] = sd;
    }

    // ---- deferred pushes: exact fp32 z recheck of both halves of hit pairs ----
    while (maskP) {
        int pr = __ffs(maskP) - 1;
        maskP &= maskP - 1;
        int i = pr >> 1, p = pr & 1;
        int base = (((i * NT) + tid) << 2) + p * 2;
        #pragma unroll
        for (int h = 0; h < 2; h++) {
            int idx = base + h;
            float xx = __ldg(xrow + idx);
            float zz = fmaf(xx, __ldg(g_rstd + idx), __ldg(g_nmr + idx));
            float az = fabsf(zz);
            if (az > TH_TOP) {
                int q = atomicAdd(&s_cnt[0], 1);
                if (q < CAPT) { s_tz[q] = zz; s_ti[q] = idx; }
            } else if (az < TH_BOT) {
                int q = atomicAdd(&s_cnt[1], 1);
                if (q < CAPB) { s_bz[q] = az; s_bi[q] = idx; }
            }
        }
    }
    __syncthreads();   // barrier A

    // ---- rare retry loop (block-uniform, exact rescan; normally breaks) ----
    {
        float thT = TH_TOP, thB = TH_BOT;
        for (int tries = 0; tries < 12; ++tries) {
            int ct = s_cnt[0], cb = s_cnt[1];
            bool badT = (ct < K16) | (ct > CAPT);
            bool badB = (cb < K16) | (cb > CAPB);
            if (!badT && !badB) break;
            if (badT) thT = (ct < K16) ? thT * 0.5f : thT * 1.4f;
            if (badB) thB = (cb < K16) ? thB * 2.0f : thB * 0.5f;
            __syncthreads();
            if (tid == 0) { if (badT) s_cnt[0] = 0; if (badB) s_cnt[1] = 0; }
            __syncthreads();
            for (int i = 0; i < NV4; i++) {
                int idx4 = i * NT + tid;
                float4 xv = xr[idx4];
                #pragma unroll
                for (int c = 0; c < 4; c++) {
                    int idx = idx4 * 4 + c;
                    float xx = (c==0)?xv.x:(c==1)?xv.y:(c==2)?xv.z:xv.w;
                    float zz = fmaf(xx, __ldg(g_rstd + idx), __ldg(g_nmr + idx));
                    float az = fabsf(zz);
                    if (badT && az > thT) {
                        int q = atomicAdd(&s_cnt[0], 1);
                        if (q < CAPT) { s_tz[q] = zz; s_ti[q] = idx; }
                    }
                    if (badB && az < thB) {
                        int q = atomicAdd(&s_cnt[1], 1);
                        if (q < CAPB) { s_bz[q] = az; s_bi[q] = idx; }
                    }
                }
            }
            __syncthreads();
        }
    }

    // ---- cosine gate ----
    float a = 0.f, b = 0.f;
    #pragma unroll
    for (int w = 0; w < NT / 32; w++) { a += s_part[2*w]; b += s_part[2*w+1]; }
    float inv = rsqrtf(fmaxf(a, 1e-24f));
    float cs  = fminf(fmaxf(b * g_scal[4] * inv, -1.0f), 1.0f);
    const float gc = __expf(-g_scal[0] * cs);

    // ---- bulk store: out = half(g) * gc ----
    #pragma unroll
    for (int i = 0; i < NV4; i++) {
        float2 f0 = __half22float2(gh[i*2+0]);
        float2 f1 = __half22float2(gh[i*2+1]);
        float4 ov;
        ov.x = f0.x * gc;
        ov.y = f0.y * gc;
        ov.z = f1.x * gc;
        ov.w = f1.y * gc;
        orow4[i * NT + tid] = ov;
    }
    __syncthreads();   // barrier B: bulk stores done before patching

    // ---- selection + global patch (<=32 elements) ----
    const int wid = tid >> 5, lane = tid & 31;
    if (wid == 0) {
        int ct = min(s_cnt[0], CAPT);
        float r0=-1.f,r1=-1.f,r2=-1.f,r3=-1.f,r4=-1.f,r5=-1.f,r6=-1.f,r7=-1.f;
        for (int k = lane; k < ct; k += 32) {
            float v = fabsf(s_tz[k]);
            INS8_TOP(v);
        }
        float last = -1.f;
        #pragma unroll
        for (int it = 0; it < K16; it++) {
            float m = r0;
            #pragma unroll
            for (int o = 16; o; o >>= 1) m = fmaxf(m, __shfl_xor_sync(0xffffffffu, m, o));
            last = m;
            if (r0 == m) { r0=r1; r1=r2; r2=r3; r3=r4; r4=r5; r5=r6; r6=r7; r7=-1.f; }
        }
        const float v16 = last;
        const float bu = g_scal[1];
        const float gm = g_scal[2];
        for (int k = lane; k < ct; k += 32) {
            float zz = s_tz[k];
            if (fabsf(zz) >= v16) {
                int idx = s_ti[k];
                float gate = fminf(fmaxf(fmaf(bu, tanhf(gm * zz), 1.0f), 0.1f), 8.0f);
                orow[idx] = orow[idx] * gate;
            }
        }
    } else if (wid == 1) {
        int cb = min(s_cnt[1], CAPB);
        float r0=INF,r1=INF,r2=INF,r3=INF,r4=INF,r5=INF,r6=INF,r7=INF;
        for (int k = lane; k < cb; k += 32) {
            float v = s_bz[k];
            INS8_BOT(v);
        }
        float last = INF;
        #pragma unroll
        for (int it = 0; it < K16; it++) {
            float m = r0;
            #pragma unroll
            for (int o = 16; o; o >>= 1) m = fminf(m, __shfl_xor_sync(0xffffffffu, m, o));
            last = m;
            if (r0 == m) { r0=r1; r1=r2; r2=r3; r3=r4; r4=r5; r5=r6; r6=r7; r7=INF; }
        }
        const float w16 = last;
        const float bf = g_scal[3];
        for (int k = lane; k < cb; k += 32) {
            if (s_bz[k] <= w16) {
                int idx = s_bi[k];
                orow[idx] = orow[idx] * bf;
            }
        }
    }
}

extern "C" void kernel_launch(void* const* d_in, const int* in_sizes, int n_in,
                              void* d_out, int out_size) {
    const float* x        = (const float*)d_in[0];
    const float* ema_mean = (const float*)d_in[1];
    const float* ema_sq   = (const float*)d_in[2];
    const float* ema_out  = (const float*)d_in[3];
    const float* lt       = (const float*)d_in[4];
    const float* lbu      = (const float*)d_in[5];
    const float* lg       = (const float*)d_in[6];
    const float* lbf      = (const float*)d_in[7];
    float* out = (float*)d_out;

    int rows = in_sizes[0] / DD;
    if (rows < 1) rows = 1;

    prep_kernel<<<1, 256>>>(ema_mean, ema_sq, ema_out, lt, lbu, lg, lbf);
    gelu_gate_kernel<<<rows, NT>>>(x, ema_out, out);
}

// round 11
// speedup vs baseline: 1.9619x; 1.0190x over previous
#include <cuda_runtime.h>
#include <cuda_bf16.h>
#include <cuda_fp16.h>
#include <math.h>
#include <stdint.h>

#define DD    4096
#define NT    256
#define NV4   4          // float4 groups per thread
#define K16   16
#define CAPT  224
#define CAPB  192

#define TH_TOP 2.7f
#define TH_BOT 0.02f

__device__ float    g_rstd[DD];     // exact 1/(std+eps)
__device__ float    g_nmr[DD];      // exact -mean*rstd
__device__ uint4    g_rn4[DD / 4];  // bf16 pairs: {r01, n01, r23, n23} per 4 elems
__device__ uint2    g_e2[DD / 4];   // bf16 pairs of ema_out: {e01, e23} per 4 elems
__device__ float    g_scal[8];      // 0:tau 1:beta_up 2:gamma 3:beta_fam 4:inv_norm_e

__device__ __forceinline__ float tanha(float a) {
    float r; asm("tanh.approx.f32 %0, %1;" : "=f"(r) : "f"(a)); return r;
}
__device__ __forceinline__ __nv_bfloat162 u2b(unsigned u) {
    return *reinterpret_cast<__nv_bfloat162*>(&u);
}
__device__ __forceinline__ unsigned b2u(__nv_bfloat162 h) {
    return *reinterpret_cast<unsigned*>(&h);
}

__global__ void prep_kernel(const float* __restrict__ ema_mean,
                            const float* __restrict__ ema_sq,
                            const float* __restrict__ ema_out,
                            const float* __restrict__ p_lt,
                            const float* __restrict__ p_lbu,
                            const float* __restrict__ p_lg,
                            const float* __restrict__ p_lbf) {
    __shared__ float sp[8];
    int tid = threadIdx.x;
    float acc = 0.0f;
    for (int i4 = tid; i4 < DD / 4; i4 += 256) {
        float r[4], n[4], e[4];
        #pragma unroll
        for (int c = 0; c < 4; c++) {
            int i = i4 * 4 + c;
            float m = ema_mean[i];
            float v = fmaxf(ema_sq[i] - m * m, 1e-4f);
            float rr = 1.0f / (sqrtf(v) + 1e-5f);
            float nn = -m * rr;
            g_rstd[i] = rr;
            g_nmr[i]  = nn;
            r[c] = rr; n[c] = nn;
            e[c] = ema_out[i];
            acc = fmaf(e[c], e[c], acc);
        }
        uint4 u;
        u.x = b2u(__floats2bfloat162_rn(r[0], r[1]));
        u.y = b2u(__floats2bfloat162_rn(n[0], n[1]));
        u.z = b2u(__floats2bfloat162_rn(r[2], r[3]));
        u.w = b2u(__floats2bfloat162_rn(n[2], n[3]));
        g_rn4[i4] = u;
        uint2 w;
        w.x = b2u(__floats2bfloat162_rn(e[0], e[1]));
        w.y = b2u(__floats2bfloat162_rn(e[2], e[3]));
        g_e2[i4] = w;
    }
    #pragma unroll
    for (int o = 16; o; o >>= 1) acc += __shfl_xor_sync(0xffffffffu, acc, o);
    if ((tid & 31) == 0) sp[tid >> 5] = acc;
    __syncthreads();
    if (tid == 0) {
        float s = 0.0f;
        #pragma unroll
        for (int w = 0; w < 8; w++) s += sp[w];
        g_scal[0] = expf(p_lt[0]);                        // tau
        g_scal[1] = log1pf(expf(p_lbu[0]));               // beta_up
        g_scal[2] = log1pf(expf(p_lg[0]));                // gamma
        g_scal[3] = 1.0f / (1.0f + expf(-p_lbf[0]));      // beta_fam
        g_scal[4] = 1.0f / fmaxf(sqrtf(s), 1e-12f);       // 1/||ema_out||
    }
}

// descending insert into 8-deep sorted list r0..r7
#define INS8_TOP(v) do { float _l=(v), _u;                          \
    _u=fmaxf(r0,_l); _l=fminf(r0,_l); r0=_u;                        \
    _u=fmaxf(r1,_l); _l=fminf(r1,_l); r1=_u;                        \
    _u=fmaxf(r2,_l); _l=fminf(r2,_l); r2=_u;                        \
    _u=fmaxf(r3,_l); _l=fminf(r3,_l); r3=_u;                        \
    _u=fmaxf(r4,_l); _l=fminf(r4,_l); r4=_u;                        \
    _u=fmaxf(r5,_l); _l=fminf(r5,_l); r5=_u;                        \
    _u=fmaxf(r6,_l); _l=fminf(r6,_l); r6=_u;                        \
    r7=fmaxf(r7,_l); } while(0)

#define INS8_BOT(v) do { float _l=(v), _u;                          \
    _u=fminf(r0,_l); _l=fmaxf(r0,_l); r0=_u;                        \
    _u=fminf(r1,_l); _l=fmaxf(r1,_l); r1=_u;                        \
    _u=fminf(r2,_l); _l=fmaxf(r2,_l); r2=_u;                        \
    _u=fminf(r3,_l); _l=fmaxf(r3,_l); r3=_u;                        \
    _u=fminf(r4,_l); _l=fmaxf(r4,_l); r4=_u;                        \
    _u=fminf(r5,_l); _l=fmaxf(r5,_l); r5=_u;                        \
    _u=fminf(r6,_l); _l=fmaxf(r6,_l); r6=_u;                        \
    r7=fminf(r7,_l); } while(0)

__global__ __launch_bounds__(NT, 8)
void gelu_gate_kernel(const float* __restrict__ x,
                      float* __restrict__ out) {
    __shared__ float s_tz[CAPT];
    __shared__ int   s_ti[CAPT];
    __shared__ float s_bz[CAPB];
    __shared__ int   s_bi[CAPB];
    __shared__ int   s_cnt[2];
    __shared__ float s_part[2 * (NT / 32)];

    const int tid = threadIdx.x;
    const float* xrow = x + (size_t)blockIdx.x * DD;
    const float4* xr  = reinterpret_cast<const float4*>(xrow);
    const uint4*  rn  = g_rn4;
    const uint2*  eb  = g_e2;
    float* orow = out + (size_t)blockIdx.x * DD;
    float4* orow4 = reinterpret_cast<float4*>(orow);

    const float G0 = 0.7978845608028654f;
    const float G1 = 0.044715f * 0.7978845608028654f;
    const float INF = __int_as_float(0x7f800000);
    const __nv_bfloat162 TT2 = __float2bfloat162_rn(TH_TOP);
    const __nv_bfloat162 TB2 = __float2bfloat162_rn(TH_BOT);

    if (tid == 0) { s_cnt[0] = 0; s_cnt[1] = 0; }
    __syncthreads();

    __half2 gh[2 * NV4];     // packed gelu values (8 regs)
    float s2 = 0.f, sd = 0.f;
    unsigned maskP = 0u;     // one bit per element-pair (8 pairs)

    #pragma unroll
    for (int i = 0; i < NV4; i++) {
        int idx4 = i * NT + tid;
        float4 xv = xr[idx4];
        uint4  rv = rn[idx4];
        uint2  ev = eb[idx4];
        float gg[4];
        #pragma unroll
        for (int c = 0; c < 4; c++) {
            float xx = (c==0)?xv.x:(c==1)?xv.y:(c==2)?xv.z:xv.w;
            float x2 = xx * xx;
            float u  = xx * fmaf(x2, G1, G0);
            float t  = tanha(u);
            float hx = 0.5f * xx;
            float g  = fmaf(hx, t, hx);
            s2 = fmaf(g, g, s2);
            gg[c] = g;
        }
        // sd accumulation with bf16 e (expanded to fp32)
        {
            float e0 = __bfloat162float(__low2bfloat16(u2b(ev.x)));
            float e1 = __bfloat162float(__high2bfloat16(u2b(ev.x)));
            float e2 = __bfloat162float(__low2bfloat16(u2b(ev.y)));
            float e3 = __bfloat162float(__high2bfloat16(u2b(ev.y)));
            sd = fmaf(gg[0], e0, sd);
            sd = fmaf(gg[1], e1, sd);
            sd = fmaf(gg[2], e2, sd);
            sd = fmaf(gg[3], e3, sd);
        }
        gh[i*2+0] = __floats2half2_rn(gg[0], gg[1]);
        gh[i*2+1] = __floats2half2_rn(gg[2], gg[3]);
        // bf16x2 z-filter at pair granularity
        {
            __nv_bfloat162 xp0 = __floats2bfloat162_rn(xv.x, xv.y);
            __nv_bfloat162 xp1 = __floats2bfloat162_rn(xv.z, xv.w);
            __nv_bfloat162 z0 = __hfma2(xp0, u2b(rv.x), u2b(rv.y));
            __nv_bfloat162 z1 = __hfma2(xp1, u2b(rv.z), u2b(rv.w));
            __nv_bfloat162 a0 = __habs2(z0);
            __nv_bfloat162 a1 = __habs2(z1);
            unsigned h0 = b2u(__hgt2(a0, TT2)) | b2u(__hlt2(a0, TB2));
            unsigned h1 = b2u(__hgt2(a1, TT2)) | b2u(__hlt2(a1, TB2));
            maskP |= h0 ? (1u << (i*2+0)) : 0u;
            maskP |= h1 ? (1u << (i*2+1)) : 0u;
        }
    }

    #pragma unroll
    for (int o = 16; o; o >>= 1) {
        s2 += __shfl_xor_sync(0xffffffffu, s2, o);
        sd += __shfl_xor_sync(0xffffffffu, sd, o);
    }
    if ((tid & 31) == 0) {
        s_part[(tid >> 5) * 2 + 0] = s2;
        s_part[(tid >> 5) * 2 + 1] = sd;
    }

    // ---- deferred pushes: exact fp32 z recheck of both halves of hit pairs ----
    while (maskP) {
        int pr = __ffs(maskP) - 1;
        maskP &= maskP - 1;
        int i = pr >> 1, p = pr & 1;
        int base = (((i * NT) + tid) << 2) + p * 2;
        #pragma unroll
        for (int h = 0; h < 2; h++) {
            int idx = base + h;
            float xx = __ldg(xrow + idx);
            float zz = fmaf(xx, __ldg(g_rstd + idx), __ldg(g_nmr + idx));
            float az = fabsf(zz);
            if (az > TH_TOP) {
                int q = atomicAdd(&s_cnt[0], 1);
                if (q < CAPT) { s_tz[q] = zz; s_ti[q] = idx; }
            } else if (az < TH_BOT) {
                int q = atomicAdd(&s_cnt[1], 1);
                if (q < CAPB) { s_bz[q] = az; s_bi[q] = idx; }
            }
        }
    }
    __syncthreads();   // barrier A

    // ---- rare retry loop (block-uniform, exact rescan; normally breaks) ----
    {
        float thT = TH_TOP, thB = TH_BOT;
        for (int tries = 0; tries < 12; ++tries) {
            int ct = s_cnt[0], cb = s_cnt[1];
            bool badT = (ct < K16) | (ct > CAPT);
            bool badB = (cb < K16) | (cb > CAPB);
            if (!badT && !badB) break;
            if (badT) thT = (ct < K16) ? thT * 0.5f : thT * 1.4f;
            if (badB) thB = (cb < K16) ? thB * 2.0f : thB * 0.5f;
            __syncthreads();
            if (tid == 0) { if (badT) s_cnt[0] = 0; if (badB) s_cnt[1] = 0; }
            __syncthreads();
            for (int i = 0; i < NV4; i++) {
                int idx4 = i * NT + tid;
                float4 xv = xr[idx4];
                #pragma unroll
                for (int c = 0; c < 4; c++) {
                    int idx = idx4 * 4 + c;
                    float xx = (c==0)?xv.x:(c==1)?xv.y:(c==2)?xv.z:xv.w;
                    float zz = fmaf(xx, __ldg(g_rstd + idx), __ldg(g_nmr + idx));
                    float az = fabsf(zz);
                    if (badT && az > thT) {
                        int q = atomicAdd(&s_cnt[0], 1);
                        if (q < CAPT) { s_tz[q] = zz; s_ti[q] = idx; }
                    }
                    if (badB && az < thB) {
                        int q = atomicAdd(&s_cnt[1], 1);
                        if (q < CAPB) { s_bz[q] = az; s_bi[q] = idx; }
                    }
                }
            }
            __syncthreads();
        }
    }

    // ---- cosine gate ----
    float a = 0.f, b = 0.f;
    #pragma unroll
    for (int w = 0; w < NT / 32; w++) { a += s_part[2*w]; b += s_part[2*w+1]; }
    float inv = rsqrtf(fmaxf(a, 1e-24f));
    float cs  = fminf(fmaxf(b * g_scal[4] * inv, -1.0f), 1.0f);
    const float gc = __expf(-g_scal[0] * cs);

    // ---- bulk store: out = half(g) * gc ----
    #pragma unroll
    for (int i = 0; i < NV4; i++) {
        float2 f0 = __half22float2(gh[i*2+0]);
        float2 f1 = __half22float2(gh[i*2+1]);
        float4 ov;
        ov.x = f0.x * gc;
        ov.y = f0.y * gc;
        ov.z = f1.x * gc;
        ov.w = f1.y * gc;
        orow4[i * NT + tid] = ov;
    }
    __syncthreads();   // barrier B: bulk stores done before patching

    // ---- selection + global patch (<=32 elements) ----
    const int wid = tid >> 5, lane = tid & 31;
    if (wid == 0) {
        int ct = min(s_cnt[0], CAPT);
        float r0=-1.f,r1=-1.f,r2=-1.f,r3=-1.f,r4=-1.f,r5=-1.f,r6=-1.f,r7=-1.f;
        for (int k = lane; k < ct; k += 32) {
            float v = fabsf(s_tz[k]);
            INS8_TOP(v);
        }
        float last = -1.f;
        #pragma unroll
        for (int it = 0; it < K16; it++) {
            float m = r0;
            #pragma unroll
            for (int o = 16; o; o >>= 1) m = fmaxf(m, __shfl_xor_sync(0xffffffffu, m, o));
            last = m;
            if (r0 == m) { r0=r1; r1=r2; r2=r3; r3=r4; r4=r5; r5=r6; r6=r7; r7=-1.f; }
        }
        const float v16 = last;
        const float bu = g_scal[1];
        const float gm = g_scal[2];
        for (int k = lane; k < ct; k += 32) {
            float zz = s_tz[k];
            if (fabsf(zz) >= v16) {
                int idx = s_ti[k];
                float gate = fminf(fmaxf(fmaf(bu, tanhf(gm * zz), 1.0f), 0.1f), 8.0f);
                orow[idx] = orow[idx] * gate;
            }
        }
    } else if (wid == 1) {
        int cb = min(s_cnt[1], CAPB);
        float r0=INF,r1=INF,r2=INF,r3=INF,r4=INF,r5=INF,r6=INF,r7=INF;
        for (int k = lane; k < cb; k += 32) {
            float v = s_bz[k];
            INS8_BOT(v);
        }
        float last = INF;
        #pragma unroll
        for (int it = 0; it < K16; it++) {
            float m = r0;
            #pragma unroll
            for (int o = 16; o; o >>= 1) m = fminf(m, __shfl_xor_sync(0xffffffffu, m, o));
            last = m;
            if (r0 == m) { r0=r1; r1=r2; r2=r3; r3=r4; r4=r5; r5=r6; r6=r7; r7=INF; }
        }
        const float w16 = last;
        const float bf = g_scal[3];
        for (int k = lane; k < cb; k += 32) {
            if (s_bz[k] <= w16) {
                int idx = s_bi[k];
                orow[idx] = orow[idx] * bf;
            }
        }
    }
}

extern "C" void kernel_launch(void* const* d_in, const int* in_sizes, int n_in,
                              void* d_out, int out_size) {
    const float* x        = (const float*)d_in[0];
    const float* ema_mean = (const float*)d_in[1];
    const float* ema_sq   = (const float*)d_in[2];
    const float* ema_out  = (const float*)d_in[3];
    const float* lt       = (const float*)d_in[4];
    const float* lbu      = (const float*)d_in[5];
    const float* lg       = (const float*)d_in[6];
    const float* lbf      = (const float*)d_in[7];
    float* out = (float*)d_out;

    int rows = in_sizes[0] / DD;
    if (rows < 1) rows = 1;

    prep_kernel<<<1, 256>>>(ema_mean, ema_sq, ema_out, lt, lbu, lg, lbf);
    gelu_gate_kernel<<<rows, NT>>>(x, out);
}